// round 16
// baseline (speedup 1.0000x reference)
#include <cuda_runtime.h>
#include <cuda_bf16.h>

// out[b, d] = x[b, d] * clamp(diagonal[d], -0.95, 0.95)
// BATCH = 16384, LATENT_DIM = 8192, fp32. 1 GiB streamed, HBM-bound.
//
// R16: final untested store policy — __stwt (write-through). Completes
// the policy set: write-back (R9, worst), __stcs evict-first (best so
// far, 6.74-6.77 TB/s), write-through (this round). Mechanism: .wt
// streams store sectors to the DRAM write queue without dirty-line
// eviction scheduling; R9 showed "more immediate writeback = better",
// and .wt is the extreme of that axis. Geometry unchanged from the
// terminal config (MLP=4, TPB=256, grid (2,16384), 82.5% occ).

#define LATENT_DIM 8192
#define BATCH 16384
#define COLS4 (LATENT_DIM / 4)        // 2048 float4 per row
#define TPB 256
#define UNROLL 4
#define CHUNK (TPB * UNROLL)          // 1024 float4 per block
#define BLOCKS_X (COLS4 / CHUNK)      // 2 column-blocks per row

__global__ __launch_bounds__(TPB)
void diag_linear_kernel(const float4* __restrict__ x,
                        const float4* __restrict__ diag,
                        float4* __restrict__ out) {
    const int base_col = blockIdx.x * CHUNK + threadIdx.x;   // warp-coalesced
    const long long off = (long long)blockIdx.y * COLS4 + base_col;

    // 4 independent front-batched DRAM reads (MLP=4), evict-first: x is
    // read exactly once.
    float4 v[UNROLL];
#pragma unroll
    for (int k = 0; k < UNROLL; k++)
        v[k] = __ldcs(&x[off + k * TPB]);

    // Clamped diagonal: 32 KiB, L1/L2-resident after the first wave.
#pragma unroll
    for (int k = 0; k < UNROLL; k++) {
        float4 s = __ldg(&diag[base_col + k * TPB]);
        s.x = fminf(fmaxf(s.x, -0.95f), 0.95f);
        s.y = fminf(fmaxf(s.y, -0.95f), 0.95f);
        s.z = fminf(fmaxf(s.z, -0.95f), 0.95f);
        s.w = fminf(fmaxf(s.w, -0.95f), 0.95f);
        v[k].x *= s.x;
        v[k].y *= s.y;
        v[k].z *= s.z;
        v[k].w *= s.w;
    }

    // Write-through stores: stream straight toward DRAM, no dirty-line
    // eviction scheduling in L2.
#pragma unroll
    for (int k = 0; k < UNROLL; k++)
        __stwt(&out[off + k * TPB], v[k]);
}

extern "C" void kernel_launch(void* const* d_in, const int* in_sizes, int n_in,
                              void* d_out, int out_size) {
    const float4* x    = (const float4*)d_in[0];
    const float4* diag = (const float4*)d_in[1];
    float4* out        = (float4*)d_out;

    dim3 grid(BLOCKS_X, BATCH, 1);
    diag_linear_kernel<<<grid, TPB>>>(x, diag, out);
}

// round 17
// speedup vs baseline: 1.0043x; 1.0043x over previous
#include <cuda_runtime.h>
#include <cuda_bf16.h>

// out[b, d] = x[b, d] * clamp(diagonal[d], -0.95, 0.95)
// BATCH = 16384, LATENT_DIM = 8192, fp32. 1 GiB streamed, HBM-bound.
//
// TERMINAL KERNEL — final, reverted from the R16 __stwt probe.
// Sixteen rounds produced a complete bracketed map of the search space:
//   store policy: __stcs > __stwt > write-back      (span 1.1%)
//   MLP/thread:   4 ~= 8 > 16 > 1                   (span 4%)
//   occupancy:    flat >= 50%, regresses below
//   vector width / read hints / geometry / ordering / persistence: neutral
// Six draws of this binary: wall 157.25-157.73 us (sigma ~0.17),
// DRAM 83.9-85.4% active, 6.65-6.76 TB/s — the B300 DRAM read/write-
// turnaround floor for a 1:1 streaming mix. Traffic is minimal (each of
// the 2 x 512 MiB moved exactly once, fully coalesced, diag cache-hot).
//
// Config: float4 streams, MLP=4, TPB=256, grid (2, 16384), regs=32
// -> 82.5% occupancy, __ldcs reads (read-once), __stcs writes.

#define LATENT_DIM 8192
#define BATCH 16384
#define COLS4 (LATENT_DIM / 4)        // 2048 float4 per row
#define TPB 256
#define UNROLL 4
#define CHUNK (TPB * UNROLL)          // 1024 float4 per block
#define BLOCKS_X (COLS4 / CHUNK)      // 2 column-blocks per row

__global__ __launch_bounds__(TPB)
void diag_linear_kernel(const float4* __restrict__ x,
                        const float4* __restrict__ diag,
                        float4* __restrict__ out) {
    const int base_col = blockIdx.x * CHUNK + threadIdx.x;   // warp-coalesced
    const long long off = (long long)blockIdx.y * COLS4 + base_col;

    // 4 independent front-batched DRAM reads (MLP=4), evict-first: x is
    // read exactly once.
    float4 v[UNROLL];
#pragma unroll
    for (int k = 0; k < UNROLL; k++)
        v[k] = __ldcs(&x[off + k * TPB]);

    // Clamped diagonal: 32 KiB, L1/L2-resident after the first wave.
#pragma unroll
    for (int k = 0; k < UNROLL; k++) {
        float4 s = __ldg(&diag[base_col + k * TPB]);
        s.x = fminf(fmaxf(s.x, -0.95f), 0.95f);
        s.y = fminf(fmaxf(s.y, -0.95f), 0.95f);
        s.z = fminf(fmaxf(s.z, -0.95f), 0.95f);
        s.w = fminf(fmaxf(s.w, -0.95f), 0.95f);
        v[k].x *= s.x;
        v[k].y *= s.y;
        v[k].z *= s.z;
        v[k].w *= s.w;
    }

    // Streaming stores: output never re-read; __stcs measured best of
    // {cs, wt, wb}.
#pragma unroll
    for (int k = 0; k < UNROLL; k++)
        __stcs(&out[off + k * TPB], v[k]);
}

extern "C" void kernel_launch(void* const* d_in, const int* in_sizes, int n_in,
                              void* d_out, int out_size) {
    const float4* x    = (const float4*)d_in[0];
    const float4* diag = (const float4*)d_in[1];
    float4* out        = (float4*)d_out;

    dim3 grid(BLOCKS_X, BATCH, 1);
    diag_linear_kernel<<<grid, TPB>>>(x, diag, out);
}